// round 8
// baseline (speedup 1.0000x reference)
#include <cuda_runtime.h>
#include <cuda_fp16.h>
#include <cstdint>

#define CIN  1024
#define COUT 1024
#define MAX_M 16384

// ---------------- device global scratch (allocation-free) ----------------
__device__ float  g_W[COUT * CIN];       // densified fp32 W
__device__ __half g_Whi[COUT * CIN];     // fp16 round of W
__device__ __half g_Ahi[MAX_M * CIN];    // fp16 round of x

// ---------------- PTX helpers (vanilla sm_80 features only) ----------------
__device__ __forceinline__ uint32_t smem_u32(const void* p) {
    uint32_t a;
    asm("{ .reg .u64 t; cvta.to.shared.u64 t, %1; cvt.u32.u64 %0, t; }"
        : "=r"(a) : "l"(p));
    return a;
}
__device__ __forceinline__ void cpa16(uint32_t dst, const void* src) {
    asm volatile("cp.async.cg.shared.global [%0], [%1], 16;" :: "r"(dst), "l"(src));
}
__device__ __forceinline__ void cp_commit() {
    asm volatile("cp.async.commit_group;" ::: "memory");
}
template<int N> __device__ __forceinline__ void cp_wait() {
    asm volatile("cp.async.wait_group %0;" :: "n"(N) : "memory");
}
__device__ __forceinline__ void ldsm_x4(uint32_t& r0, uint32_t& r1, uint32_t& r2,
                                        uint32_t& r3, uint32_t addr) {
    asm volatile("ldmatrix.sync.aligned.m8n8.x4.shared.b16 {%0,%1,%2,%3}, [%4];"
                 : "=r"(r0), "=r"(r1), "=r"(r2), "=r"(r3) : "r"(addr));
}
__device__ __forceinline__ void mma_f16(float* c, const uint32_t* a, const uint32_t* b) {
    asm volatile(
        "mma.sync.aligned.m16n8k16.row.col.f32.f16.f16.f32 "
        "{%0,%1,%2,%3}, {%4,%5,%6,%7}, {%8,%9}, {%0,%1,%2,%3};"
        : "+f"(c[0]), "+f"(c[1]), "+f"(c[2]), "+f"(c[3])
        : "r"(a[0]), "r"(a[1]), "r"(a[2]), "r"(a[3]), "r"(b[0]), "r"(b[1]));
}

// ---------------- preprocessing kernels ----------------
__global__ void zero_W_kernel() {
    int i = blockIdx.x * blockDim.x + threadIdx.x;
    reinterpret_cast<float4*>(g_W)[i] = make_float4(0.f, 0.f, 0.f, 0.f);
}

__global__ void scatter_W_kernel(const float* __restrict__ vals,
                                 const int* __restrict__ idx, int nnz) {
    int i = blockIdx.x * blockDim.x + threadIdx.x;
    if (i < nnz) {
        int r = idx[i];
        int c = idx[nnz + i];
        atomicAdd(&g_W[r * CIN + c], vals[i]);
    }
}

// Fused fp32->fp16 conversion for A (from x) and W (from g_W).
__global__ void convert_AW_kernel(const float* __restrict__ x, int nA8) {
    int i = blockIdx.x * blockDim.x + threadIdx.x;
    const float4* src;
    __half* dst;
    int j;
    if (i < nA8) { src = reinterpret_cast<const float4*>(x); dst = g_Ahi; j = i; }
    else         { src = reinterpret_cast<const float4*>(g_W); dst = g_Whi; j = i - nA8; }
    float4 v0 = src[2 * j + 0];
    float4 v1 = src[2 * j + 1];
    __half2 h0 = __float22half2_rn(make_float2(v0.x, v0.y));
    __half2 h1 = __float22half2_rn(make_float2(v0.z, v0.w));
    __half2 h2 = __float22half2_rn(make_float2(v1.x, v1.y));
    __half2 h3 = __float22half2_rn(make_float2(v1.z, v1.w));
    uint4 o;
    o.x = *reinterpret_cast<uint32_t*>(&h0);
    o.y = *reinterpret_cast<uint32_t*>(&h1);
    o.z = *reinterpret_cast<uint32_t*>(&h2);
    o.w = *reinterpret_cast<uint32_t*>(&h3);
    reinterpret_cast<uint4*>(dst)[j] = o;
}

// ---------------- fp16 mma.sync GEMM, single pass ----------------
// out[m,n] = sum_k Ahi[m,k] * Whi[n,k]
// CTA tile 128x128, BK=64; 128 threads = 4 warps in 2(M)x2(N); warp 64x64.
// Fragment SMEM traffic: each operand tile read by only 2 warps (33% less
// crossbar load than the 8-warp 64x32 layout). 2 CTAs/SM (221KB smem total).
#define BK 64
#define ROWB 144
#define TILE_BYTES (128 * ROWB)          // 18432 per operand
#define STAGE_BYTES (2 * TILE_BYTES)     // 36864
#define NSTAGE 3
#define SMEM_TOTAL (NSTAGE * STAGE_BYTES)   // 110592 -> 2 CTAs = 221184B/SM
#define K_ITERS 16                       // 1024 / 64

__global__ void __launch_bounds__(128, 2)
gemm_f16_kernel(float* __restrict__ out) {
    extern __shared__ char smem_raw[];
    const uint32_t sbase = smem_u32(smem_raw);
    const int tid  = threadIdx.x;
    const int lane = tid & 31;
    const int wid  = tid >> 5;         // 0..3
    const int wm   = (wid & 1) * 64;   // warp M offset
    const int wn   = (wid >> 1) * 64;  // warp N offset
    const int m0   = blockIdx.y * 128;
    const int n0   = blockIdx.x * 128;

    float acc[4][8][4];
#pragma unroll
    for (int mi = 0; mi < 4; mi++)
#pragma unroll
        for (int ni = 0; ni < 8; ni++)
#pragma unroll
            for (int q = 0; q < 4; q++) acc[mi][ni][q] = 0.f;

    auto load_stage = [&](int j) {
        const int kk = j * BK;
        const uint32_t aS = sbase + (j % NSTAGE) * STAGE_BYTES;
        const uint32_t bS = aS + TILE_BYTES;
        // each operand: 128 rows x 8 x 16B = 1024 chunks; 8 per thread
#pragma unroll
        for (int t = 0; t < 8; t++) {
            int c = tid + t * 128;
            int row = c >> 3, kc = c & 7;
            cpa16(aS + row * ROWB + kc * 16,
                  g_Ahi + (size_t)(m0 + row) * CIN + kk + kc * 8);
            cpa16(bS + row * ROWB + kc * 16,
                  g_Whi + (size_t)(n0 + row) * CIN + kk + kc * 8);
        }
        cp_commit();
    };

    load_stage(0);
    load_stage(1);

#pragma unroll 1
    for (int it = 0; it < K_ITERS; it++) {
        if (it == K_ITERS - 1) cp_wait<0>();
        else                   cp_wait<1>();
        __syncthreads();
        if (it + 2 < K_ITERS) load_stage(it + 2);

        const uint32_t aS = sbase + (it % NSTAGE) * STAGE_BYTES;
        const uint32_t bS = aS + TILE_BYTES;
#pragma unroll
        for (int ks = 0; ks < 4; ks++) {       // four k16 steps per BK=64
            uint32_t a[4][4], b[8][2];
#pragma unroll
            for (int mi = 0; mi < 4; mi++)
                ldsm_x4(a[mi][0], a[mi][1], a[mi][2], a[mi][3],
                        aS + (wm + mi * 16 + (lane & 15)) * ROWB
                           + ks * 32 + (lane >> 4) * 16);
#pragma unroll
            for (int pr = 0; pr < 4; pr++) {
                int t = lane >> 3;
                int row = wn + pr * 16 + ((t >> 1) << 3) + (lane & 7);
                ldsm_x4(b[2 * pr][0], b[2 * pr][1],
                        b[2 * pr + 1][0], b[2 * pr + 1][1],
                        bS + row * ROWB + ks * 32 + (t & 1) * 16);
            }
#pragma unroll
            for (int mi = 0; mi < 4; mi++)
#pragma unroll
                for (int ni = 0; ni < 8; ni++)
                    mma_f16(acc[mi][ni], a[mi], b[ni]);
        }
    }

    // epilogue: direct float2 stores
    const int g = lane >> 2, i2 = (lane & 3) * 2;
#pragma unroll
    for (int mi = 0; mi < 4; mi++) {
        const int row = m0 + wm + mi * 16 + g;
        float* o0 = out + (size_t)row * COUT + n0 + wn;
        float* o1 = o0 + 8 * COUT;
#pragma unroll
        for (int ni = 0; ni < 8; ni++) {
            *reinterpret_cast<float2*>(o0 + ni * 8 + i2) =
                make_float2(acc[mi][ni][0], acc[mi][ni][1]);
            *reinterpret_cast<float2*>(o1 + ni * 8 + i2) =
                make_float2(acc[mi][ni][2], acc[mi][ni][3]);
        }
    }
}

// ---------------- launch ----------------
extern "C" void kernel_launch(void* const* d_in, const int* in_sizes, int n_in,
                              void* d_out, int out_size) {
    const float* x    = (const float*)d_in[0];   // [4, 4096, CIN] fp32
    const float* vals = (const float*)d_in[1];   // [nnz] fp32
    const int*   idx  = (const int*)d_in[2];     // [2, nnz] int32
    float* out = (float*)d_out;                  // [M, COUT] fp32

    const int nnz = in_sizes[1];
    const int M   = in_sizes[0] / CIN;           // 16384

    zero_W_kernel<<<(COUT * CIN / 4) / 256, 256>>>();
    scatter_W_kernel<<<(nnz + 255) / 256, 256>>>(vals, idx, nnz);

    const int nA8 = (M * CIN) / 8;
    const int nW8 = (COUT * CIN) / 8;
    convert_AW_kernel<<<(nA8 + nW8 + 255) / 256, 256>>>(x, nA8);

    static int smem_set = 0;
    if (!smem_set) {
        cudaFuncSetAttribute(gemm_f16_kernel,
                             cudaFuncAttributeMaxDynamicSharedMemorySize, SMEM_TOTAL);
        smem_set = 1;
    }
    dim3 grid(COUT / 128, M / 128);   // x = n fastest -> wave shares W tiles in L2
    gemm_f16_kernel<<<grid, 128, SMEM_TOTAL>>>(out);
}

// round 9
// speedup vs baseline: 1.0970x; 1.0970x over previous
#include <cuda_runtime.h>
#include <cuda_fp16.h>
#include <cstdint>

#define CIN  1024
#define COUT 1024
#define MAX_M 16384

// ---------------- device global scratch (allocation-free) ----------------
__device__ float  g_W[COUT * CIN];       // densified fp32 W
__device__ __half g_Whi[COUT * CIN];     // fp16 round of W
__device__ __half g_Ahi[MAX_M * CIN];    // fp16 round of x

// ---------------- PTX helpers (vanilla sm_80 features only) ----------------
__device__ __forceinline__ uint32_t smem_u32(const void* p) {
    uint32_t a;
    asm("{ .reg .u64 t; cvta.to.shared.u64 t, %1; cvt.u32.u64 %0, t; }"
        : "=r"(a) : "l"(p));
    return a;
}
__device__ __forceinline__ void cpa16(uint32_t dst, const void* src) {
    asm volatile("cp.async.cg.shared.global [%0], [%1], 16;" :: "r"(dst), "l"(src));
}
__device__ __forceinline__ void cp_commit() {
    asm volatile("cp.async.commit_group;" ::: "memory");
}
template<int N> __device__ __forceinline__ void cp_wait() {
    asm volatile("cp.async.wait_group %0;" :: "n"(N) : "memory");
}
__device__ __forceinline__ void ldsm_x4(uint32_t& r0, uint32_t& r1, uint32_t& r2,
                                        uint32_t& r3, uint32_t addr) {
    asm volatile("ldmatrix.sync.aligned.m8n8.x4.shared.b16 {%0,%1,%2,%3}, [%4];"
                 : "=r"(r0), "=r"(r1), "=r"(r2), "=r"(r3) : "r"(addr));
}
__device__ __forceinline__ void mma_f16(float* c, const uint32_t* a, const uint32_t* b) {
    asm volatile(
        "mma.sync.aligned.m16n8k16.row.col.f32.f16.f16.f32 "
        "{%0,%1,%2,%3}, {%4,%5,%6,%7}, {%8,%9}, {%0,%1,%2,%3};"
        : "+f"(c[0]), "+f"(c[1]), "+f"(c[2]), "+f"(c[3])
        : "r"(a[0]), "r"(a[1]), "r"(a[2]), "r"(a[3]), "r"(b[0]), "r"(b[1]));
}

// ---------------- preprocessing kernels ----------------
__global__ void zero_W_kernel() {
    int i = blockIdx.x * blockDim.x + threadIdx.x;   // 131072 threads, 2 float4 each
    float4 z = make_float4(0.f, 0.f, 0.f, 0.f);
    reinterpret_cast<float4*>(g_W)[2 * i + 0] = z;
    reinterpret_cast<float4*>(g_W)[2 * i + 1] = z;
}

__global__ void scatter_W_kernel(const float* __restrict__ vals,
                                 const int* __restrict__ idx, int nnz) {
    int i = blockIdx.x * blockDim.x + threadIdx.x;
    if (i < nnz) {
        int r = idx[i];
        int c = idx[nnz + i];
        atomicAdd(&g_W[r * CIN + c], vals[i]);
    }
}

// Fused fp32->fp16 conversion for A (from x) and W (from g_W).
// 16 floats/thread: 4 float4 loads -> 2 uint4 stores.
__global__ void convert_AW_kernel(const float* __restrict__ x, int nA16) {
    int i = blockIdx.x * blockDim.x + threadIdx.x;
    const float4* src;
    __half* dst;
    int j;
    if (i < nA16) { src = reinterpret_cast<const float4*>(x);   dst = g_Ahi; j = i; }
    else          { src = reinterpret_cast<const float4*>(g_W); dst = g_Whi; j = i - nA16; }
#pragma unroll
    for (int h = 0; h < 2; h++) {
        float4 v0 = src[4 * j + 2 * h + 0];
        float4 v1 = src[4 * j + 2 * h + 1];
        __half2 h0 = __float22half2_rn(make_float2(v0.x, v0.y));
        __half2 h1 = __float22half2_rn(make_float2(v0.z, v0.w));
        __half2 h2 = __float22half2_rn(make_float2(v1.x, v1.y));
        __half2 h3 = __float22half2_rn(make_float2(v1.z, v1.w));
        uint4 o;
        o.x = *reinterpret_cast<uint32_t*>(&h0);
        o.y = *reinterpret_cast<uint32_t*>(&h1);
        o.z = *reinterpret_cast<uint32_t*>(&h2);
        o.w = *reinterpret_cast<uint32_t*>(&h3);
        reinterpret_cast<uint4*>(dst)[2 * j + h] = o;
    }
}

// ---------------- fp16 mma.sync GEMM, single pass (R6 config) -------------
// out[m,n] = sum_k Ahi[m,k] * Whi[n,k]
// BM=BN=128, BK=64. 256 thr = 8 warps in 2(M)x4(N); warp tile 64x32.
// ROWB=144: conflict-free ldmatrix + STS. NSTAGE=3, 110.6KB, 2 CTAs/SM.
#define BK 64
#define ROWB 144
#define TILE_BYTES (128 * ROWB)          // 18432 per operand
#define STAGE_BYTES (2 * TILE_BYTES)     // 36864
#define NSTAGE 3
#define SMEM_TOTAL (NSTAGE * STAGE_BYTES)   // 110592
#define K_ITERS 16                       // 1024 / 64

__global__ void __launch_bounds__(256, 2)
gemm_f16_kernel(float* __restrict__ out) {
    extern __shared__ char smem_raw[];
    const uint32_t sbase = smem_u32(smem_raw);
    const int tid  = threadIdx.x;
    const int lane = tid & 31;
    const int wid  = tid >> 5;
    const int wm   = (wid & 1) * 64;   // warp M offset
    const int wn   = (wid >> 1) * 32;  // warp N offset
    const int m0   = blockIdx.y * 128;
    const int n0   = blockIdx.x * 128;

    float acc[4][4][4];
#pragma unroll
    for (int mi = 0; mi < 4; mi++)
#pragma unroll
        for (int ni = 0; ni < 4; ni++)
#pragma unroll
            for (int q = 0; q < 4; q++) acc[mi][ni][q] = 0.f;

    auto load_stage = [&](int j) {
        const int kk = j * BK;
        const uint32_t aS = sbase + (j % NSTAGE) * STAGE_BYTES;
        const uint32_t bS = aS + TILE_BYTES;
#pragma unroll
        for (int t = 0; t < 4; t++) {
            int c = tid + t * 256;
            int row = c >> 3, kc = c & 7;
            cpa16(aS + row * ROWB + kc * 16,
                  g_Ahi + (size_t)(m0 + row) * CIN + kk + kc * 8);
            cpa16(bS + row * ROWB + kc * 16,
                  g_Whi + (size_t)(n0 + row) * CIN + kk + kc * 8);
        }
        cp_commit();
    };

    // fragment loads for one k16 step
    auto frag_load = [&](uint32_t aS, uint32_t bS, int ks,
                         uint32_t a[4][4], uint32_t b[4][2]) {
#pragma unroll
        for (int mi = 0; mi < 4; mi++)
            ldsm_x4(a[mi][0], a[mi][1], a[mi][2], a[mi][3],
                    aS + (wm + mi * 16 + (lane & 15)) * ROWB
                       + ks * 32 + (lane >> 4) * 16);
#pragma unroll
        for (int pr = 0; pr < 2; pr++) {
            int t = lane >> 3;
            int row = wn + pr * 16 + ((t >> 1) << 3) + (lane & 7);
            ldsm_x4(b[2 * pr][0], b[2 * pr][1],
                    b[2 * pr + 1][0], b[2 * pr + 1][1],
                    bS + row * ROWB + ks * 32 + (t & 1) * 16);
        }
    };

    load_stage(0);
    load_stage(1);

#pragma unroll 1
    for (int it = 0; it < K_ITERS; it++) {
        if (it == K_ITERS - 1) cp_wait<0>();
        else                   cp_wait<1>();
        __syncthreads();

        const uint32_t aS = sbase + (it % NSTAGE) * STAGE_BYTES;
        const uint32_t bS = aS + TILE_BYTES;

        // ks=0 fragments FIRST (starts the tensor chain), then next-stage
        // cp.async burst overlaps with ks=0 MMAs.
        uint32_t a[4][4], b[4][2];
        frag_load(aS, bS, 0, a, b);
        if (it + 2 < K_ITERS) load_stage(it + 2);
#pragma unroll
        for (int mi = 0; mi < 4; mi++)
#pragma unroll
            for (int ni = 0; ni < 4; ni++)
                mma_f16(acc[mi][ni], a[mi], b[ni]);

#pragma unroll
        for (int ks = 1; ks < 4; ks++) {
            frag_load(aS, bS, ks, a, b);
#pragma unroll
            for (int mi = 0; mi < 4; mi++)
#pragma unroll
                for (int ni = 0; ni < 4; ni++)
                    mma_f16(acc[mi][ni], a[mi], b[ni]);
        }
    }

    // epilogue: direct float2 stores
    const int g = lane >> 2, i2 = (lane & 3) * 2;
#pragma unroll
    for (int mi = 0; mi < 4; mi++) {
        const int row = m0 + wm + mi * 16 + g;
        float* o0 = out + (size_t)row * COUT + n0 + wn;
        float* o1 = o0 + 8 * COUT;
#pragma unroll
        for (int ni = 0; ni < 4; ni++) {
            *reinterpret_cast<float2*>(o0 + ni * 8 + i2) =
                make_float2(acc[mi][ni][0], acc[mi][ni][1]);
            *reinterpret_cast<float2*>(o1 + ni * 8 + i2) =
                make_float2(acc[mi][ni][2], acc[mi][ni][3]);
        }
    }
}

// ---------------- launch ----------------
extern "C" void kernel_launch(void* const* d_in, const int* in_sizes, int n_in,
                              void* d_out, int out_size) {
    const float* x    = (const float*)d_in[0];   // [4, 4096, CIN] fp32
    const float* vals = (const float*)d_in[1];   // [nnz] fp32
    const int*   idx  = (const int*)d_in[2];     // [2, nnz] int32
    float* out = (float*)d_out;                  // [M, COUT] fp32

    const int nnz = in_sizes[1];
    const int M   = in_sizes[0] / CIN;           // 16384

    zero_W_kernel<<<(COUT * CIN / 8) / 256, 256>>>();
    scatter_W_kernel<<<(nnz + 255) / 256, 256>>>(vals, idx, nnz);

    const int nA16 = (M * CIN) / 16;
    const int nW16 = (COUT * CIN) / 16;
    convert_AW_kernel<<<(nA16 + nW16 + 255) / 256, 256>>>(x, nA16);

    static int smem_set = 0;
    if (!smem_set) {
        cudaFuncSetAttribute(gemm_f16_kernel,
                             cudaFuncAttributeMaxDynamicSharedMemorySize, SMEM_TOTAL);
        smem_set = 1;
    }
    dim3 grid(COUT / 128, M / 128);   // x = n fastest -> wave shares W tiles in L2
    gemm_f16_kernel<<<grid, 128 * 2, SMEM_TOTAL>>>(out);
}